// round 1
// baseline (speedup 1.0000x reference)
#include <cuda_runtime.h>

#define BB  4
#define SS  2048
#define DD  1024
#define HH  16
#define DKK 64
#define NN  (BB*SS)
#define AST 68   // attn smem row stride (floats)

// Scratch (static __device__ per allocation rules): q,k,v projected [B,H,S,DK], concat [B,S,D]
__device__ float g_q[BB*HH*SS*DKK];
__device__ float g_k[BB*HH*SS*DKK];
__device__ float g_v[BB*HH*SS*DKK];
__device__ float g_c[NN*DD];

// ---------------------------------------------------------------------------
// Projection: P[b,h,s,k] = sum_d X[b,s,d] * W[h,d,k]
// Block tile: 128 rows (s) x 64 cols (DK), BK=16. 256 threads, 8x4 microtile.
// ---------------------------------------------------------------------------
__global__ __launch_bounds__(256, 4)
void proj_kernel(const float* __restrict__ X, const float* __restrict__ W,
                 float* __restrict__ P)
{
    __shared__ float As[16][132];   // transposed A tile [kk][row], padded
    __shared__ float Bs[16][64];    // natural B tile [kk][col]

    const int tid = threadIdx.x;
    const int ty  = tid >> 4;       // 0..15 -> rows ty*8..+7
    const int tx  = tid & 15;       // 0..15 -> cols tx*4..+3
    const int s0  = blockIdx.x * 128;
    const int h   = blockIdx.y;
    const int b   = blockIdx.z;

    const float* Xb = X + (size_t)b * SS * DD + (size_t)s0 * DD;
    const float* Wh = W + (size_t)h * DD * DKK;

    float acc[8][4];
    #pragma unroll
    for (int i = 0; i < 8; i++)
        #pragma unroll
        for (int j = 0; j < 4; j++) acc[i][j] = 0.f;

    for (int d0 = 0; d0 < DD; d0 += 16) {
        if (d0 != 0) __syncthreads();
        // A tile 128x16 -> transposed store
        #pragma unroll
        for (int u = 0; u < 2; u++) {
            int f   = tid + u * 256;
            int row = f >> 2, c4 = f & 3;
            float4 a = *reinterpret_cast<const float4*>(Xb + (size_t)row * DD + d0 + c4 * 4);
            As[c4*4+0][row] = a.x;
            As[c4*4+1][row] = a.y;
            As[c4*4+2][row] = a.z;
            As[c4*4+3][row] = a.w;
        }
        // B tile 16x64 natural
        {
            int f  = tid;
            int dr = f >> 4, c4 = f & 15;
            float4 bv = *reinterpret_cast<const float4*>(Wh + (size_t)(d0 + dr) * DKK + c4 * 4);
            *reinterpret_cast<float4*>(&Bs[dr][c4*4]) = bv;
        }
        __syncthreads();

        #pragma unroll
        for (int kk = 0; kk < 16; kk++) {
            float4 a0 = *reinterpret_cast<const float4*>(&As[kk][ty*8]);
            float4 a1 = *reinterpret_cast<const float4*>(&As[kk][ty*8+4]);
            float4 b4 = *reinterpret_cast<const float4*>(&Bs[kk][tx*4]);
            float a[8] = {a0.x,a0.y,a0.z,a0.w,a1.x,a1.y,a1.z,a1.w};
            float bv[4] = {b4.x,b4.y,b4.z,b4.w};
            #pragma unroll
            for (int i = 0; i < 8; i++)
                #pragma unroll
                for (int j = 0; j < 4; j++)
                    acc[i][j] = fmaf(a[i], bv[j], acc[i][j]);
        }
    }

    float* Pb = P + ((size_t)(b * HH + h) * SS + s0) * DKK;
    #pragma unroll
    for (int i = 0; i < 8; i++) {
        float4 o = make_float4(acc[i][0], acc[i][1], acc[i][2], acc[i][3]);
        *reinterpret_cast<float4*>(Pb + (size_t)(ty*8+i) * DKK + tx*4) = o;
    }
}

// ---------------------------------------------------------------------------
// Causal flash attention, fp32. One block = 64 q-rows of one (b,h).
// Online softmax; scale = DK/sqrt(DK) = 8.
// ---------------------------------------------------------------------------
__global__ __launch_bounds__(256)
void attn_kernel(const float* __restrict__ gq, const float* __restrict__ gk,
                 const float* __restrict__ gv, float* __restrict__ gc)
{
    extern __shared__ float sm[];
    float* Qs = sm;              // [64][AST] natural  [row][kk]
    float* Ks = sm + 64*AST;     // [64][AST] transposed [kk][col]
    float* Vs = sm + 2*64*AST;   // [64][AST] natural  [t][dk]
    float* Ps = sm + 3*64*AST;   // [64][AST] natural  [row][t]

    const int tid = threadIdx.x;
    const int ty  = tid >> 4, tx = tid & 15;
    const int h   = blockIdx.y, b = blockIdx.z;
    const int st  = gridDim.x - 1 - blockIdx.x;   // big (late-diagonal) blocks first
    const int s0  = st * 64;
    const int r0  = ty * 4, c0 = tx * 4;

    const size_t base = (size_t)(b * HH + h) * SS * DKK;
    const float* qb = gq + base + (size_t)s0 * DKK;
    const float* kb = gk + base;
    const float* vb = gv + base;

    // load Q tile (64x64)
    #pragma unroll
    for (int u = 0; u < 4; u++) {
        int f = tid + u * 256;
        int row = f >> 4, c4 = f & 15;
        *reinterpret_cast<float4*>(Qs + row*AST + c4*4) =
            *reinterpret_cast<const float4*>(qb + (size_t)row * DKK + c4*4);
    }

    float m[4], l[4], o[4][4];
    #pragma unroll
    for (int i = 0; i < 4; i++) {
        m[i] = -1e30f; l[i] = 0.f;
        #pragma unroll
        for (int j = 0; j < 4; j++) o[i][j] = 0.f;
    }

    const int ntiles = st + 1;
    for (int tt = 0; tt < ntiles; ++tt) {
        const int t0 = tt * 64;
        __syncthreads();   // protect Ks/Vs/Ps from previous iteration's readers
        // load K (transposed) and V (natural)
        #pragma unroll
        for (int u = 0; u < 4; u++) {
            int f = tid + u * 256;
            int row = f >> 4, c4 = f & 15;
            float4 kv = *reinterpret_cast<const float4*>(kb + (size_t)(t0+row) * DKK + c4*4);
            Ks[(c4*4+0)*AST + row] = kv.x;
            Ks[(c4*4+1)*AST + row] = kv.y;
            Ks[(c4*4+2)*AST + row] = kv.z;
            Ks[(c4*4+3)*AST + row] = kv.w;
            *reinterpret_cast<float4*>(Vs + row*AST + c4*4) =
                *reinterpret_cast<const float4*>(vb + (size_t)(t0+row) * DKK + c4*4);
        }
        __syncthreads();

        // S = Q K^T (per-thread 4x4)
        float sv[4][4];
        #pragma unroll
        for (int i = 0; i < 4; i++)
            #pragma unroll
            for (int j = 0; j < 4; j++) sv[i][j] = 0.f;

        #pragma unroll 16
        for (int kk = 0; kk < 64; kk++) {
            float a[4];
            #pragma unroll
            for (int i = 0; i < 4; i++) a[i] = Qs[(r0+i)*AST + kk];
            float4 b4 = *reinterpret_cast<const float4*>(Ks + kk*AST + c0);
            float bv[4] = {b4.x, b4.y, b4.z, b4.w};
            #pragma unroll
            for (int i = 0; i < 4; i++)
                #pragma unroll
                for (int j = 0; j < 4; j++)
                    sv[i][j] = fmaf(a[i], bv[j], sv[i][j]);
        }

        // scale and causal mask (only diagonal tile partially masked)
        #pragma unroll
        for (int i = 0; i < 4; i++)
            #pragma unroll
            for (int j = 0; j < 4; j++) sv[i][j] *= 8.0f;
        if (t0 == s0) {
            #pragma unroll
            for (int i = 0; i < 4; i++)
                #pragma unroll
                for (int j = 0; j < 4; j++)
                    if (c0 + j > r0 + i) sv[i][j] = -1e30f;
        }

        // row max across the 16 tx lanes
        float mt[4];
        #pragma unroll
        for (int i = 0; i < 4; i++)
            mt[i] = fmaxf(fmaxf(sv[i][0], sv[i][1]), fmaxf(sv[i][2], sv[i][3]));
        #pragma unroll
        for (int off = 8; off; off >>= 1)
            #pragma unroll
            for (int i = 0; i < 4; i++)
                mt[i] = fmaxf(mt[i], __shfl_xor_sync(0xffffffffu, mt[i], off));

        float mn[4], alpha[4];
        #pragma unroll
        for (int i = 0; i < 4; i++) {
            mn[i] = fmaxf(m[i], mt[i]);
            alpha[i] = __expf(m[i] - mn[i]);
            m[i] = mn[i];
        }

        float p[4][4], ls[4];
        #pragma unroll
        for (int i = 0; i < 4; i++) {
            ls[i] = 0.f;
            #pragma unroll
            for (int j = 0; j < 4; j++) {
                p[i][j] = __expf(sv[i][j] - mn[i]);
                ls[i] += p[i][j];
            }
        }
        #pragma unroll
        for (int off = 8; off; off >>= 1)
            #pragma unroll
            for (int i = 0; i < 4; i++)
                ls[i] += __shfl_xor_sync(0xffffffffu, ls[i], off);

        #pragma unroll
        for (int i = 0; i < 4; i++) {
            l[i] = l[i] * alpha[i] + ls[i];
            #pragma unroll
            for (int j = 0; j < 4; j++) o[i][j] *= alpha[i];
        }

        // write P tile
        #pragma unroll
        for (int i = 0; i < 4; i++)
            *reinterpret_cast<float4*>(Ps + (r0+i)*AST + c0) =
                make_float4(p[i][0], p[i][1], p[i][2], p[i][3]);
        __syncthreads();

        // O += P V
        #pragma unroll 16
        for (int kk = 0; kk < 64; kk++) {
            float a[4];
            #pragma unroll
            for (int i = 0; i < 4; i++) a[i] = Ps[(r0+i)*AST + kk];
            float4 b4 = *reinterpret_cast<const float4*>(Vs + kk*AST + c0);
            float bv[4] = {b4.x, b4.y, b4.z, b4.w};
            #pragma unroll
            for (int i = 0; i < 4; i++)
                #pragma unroll
                for (int j = 0; j < 4; j++)
                    o[i][j] = fmaf(a[i], bv[j], o[i][j]);
        }
    }

    // epilogue: normalize and write concat layout [B,S,D] at head offset
    float* outp = gc + ((size_t)b * SS + s0) * DD + h * DKK;
    #pragma unroll
    for (int i = 0; i < 4; i++) {
        float inv = 1.0f / l[i];
        float4 ov = make_float4(o[i][0]*inv, o[i][1]*inv, o[i][2]*inv, o[i][3]*inv);
        *reinterpret_cast<float4*>(outp + (size_t)(r0+i) * DD + c0) = ov;
    }
}

// ---------------------------------------------------------------------------
// Output projection: C[n,i] = sum_d A[n,d]*Wo[i,d] + bo[i]
// Block tile: 128 rows x 64 cols, BK=16. 256 threads, 8x4 microtile.
// ---------------------------------------------------------------------------
__global__ __launch_bounds__(256, 4)
void outproj_kernel(const float* __restrict__ A, const float* __restrict__ Wo,
                    const float* __restrict__ bo, float* __restrict__ C)
{
    __shared__ float As[16][132];   // transposed A tile
    __shared__ float Bs[16][68];    // transposed Wo tile: Bs[kk][i] = Wo[i0+i][d0+kk]

    const int tid = threadIdx.x;
    const int ty  = tid >> 4, tx = tid & 15;
    const int n0  = blockIdx.x * 128;
    const int i0  = blockIdx.y * 64;

    const float* Ab = A + (size_t)n0 * DD;

    float acc[8][4];
    #pragma unroll
    for (int i = 0; i < 8; i++)
        #pragma unroll
        for (int j = 0; j < 4; j++) acc[i][j] = 0.f;

    for (int d0 = 0; d0 < DD; d0 += 16) {
        if (d0 != 0) __syncthreads();
        #pragma unroll
        for (int u = 0; u < 2; u++) {
            int f = tid + u * 256;
            int row = f >> 2, c4 = f & 3;
            float4 a = *reinterpret_cast<const float4*>(Ab + (size_t)row * DD + d0 + c4*4);
            As[c4*4+0][row] = a.x;
            As[c4*4+1][row] = a.y;
            As[c4*4+2][row] = a.z;
            As[c4*4+3][row] = a.w;
        }
        {
            int f = tid;
            int ii = f >> 2, c4 = f & 3;
            float4 w = *reinterpret_cast<const float4*>(Wo + (size_t)(i0+ii) * DD + d0 + c4*4);
            Bs[c4*4+0][ii] = w.x;
            Bs[c4*4+1][ii] = w.y;
            Bs[c4*4+2][ii] = w.z;
            Bs[c4*4+3][ii] = w.w;
        }
        __syncthreads();

        #pragma unroll
        for (int kk = 0; kk < 16; kk++) {
            float4 a0 = *reinterpret_cast<const float4*>(&As[kk][ty*8]);
            float4 a1 = *reinterpret_cast<const float4*>(&As[kk][ty*8+4]);
            float4 b4 = *reinterpret_cast<const float4*>(&Bs[kk][tx*4]);
            float a[8] = {a0.x,a0.y,a0.z,a0.w,a1.x,a1.y,a1.z,a1.w};
            float bv[4] = {b4.x,b4.y,b4.z,b4.w};
            #pragma unroll
            for (int i = 0; i < 8; i++)
                #pragma unroll
                for (int j = 0; j < 4; j++)
                    acc[i][j] = fmaf(a[i], bv[j], acc[i][j]);
        }
    }

    float4 bias = *reinterpret_cast<const float4*>(bo + i0 + tx*4);
    float bb[4] = {bias.x, bias.y, bias.z, bias.w};
    #pragma unroll
    for (int i = 0; i < 8; i++) {
        float4 o = make_float4(acc[i][0]+bb[0], acc[i][1]+bb[1],
                               acc[i][2]+bb[2], acc[i][3]+bb[3]);
        *reinterpret_cast<float4*>(C + (size_t)(n0 + ty*8 + i) * DD + i0 + tx*4) = o;
    }
}

// ---------------------------------------------------------------------------
extern "C" void kernel_launch(void* const* d_in, const int* in_sizes, int n_in,
                              void* d_out, int out_size)
{
    const float* Q  = (const float*)d_in[0];
    const float* K  = (const float*)d_in[1];
    const float* V  = (const float*)d_in[2];
    // d_in[3] = mask (causal tril) — structure known, unused
    const float* Wq = (const float*)d_in[4];
    const float* Wk = (const float*)d_in[5];
    const float* Wv = (const float*)d_in[6];
    const float* Wo = (const float*)d_in[7];
    const float* bo = (const float*)d_in[8];
    float* out = (float*)d_out;

    float *gq, *gk, *gv, *gc;
    cudaGetSymbolAddress((void**)&gq, g_q);
    cudaGetSymbolAddress((void**)&gk, g_k);
    cudaGetSymbolAddress((void**)&gv, g_v);
    cudaGetSymbolAddress((void**)&gc, g_c);

    dim3 pg(SS/128, HH, BB);
    proj_kernel<<<pg, 256>>>(Q, Wq, gq);
    proj_kernel<<<pg, 256>>>(K, Wk, gk);
    proj_kernel<<<pg, 256>>>(V, Wv, gv);

    int smem = 4 * 64 * AST * (int)sizeof(float);   // 69632 B
    cudaFuncSetAttribute(attn_kernel, cudaFuncAttributeMaxDynamicSharedMemorySize, smem);
    attn_kernel<<<dim3(SS/64, HH, BB), 256, smem>>>(gq, gk, gv, gc);

    outproj_kernel<<<dim3(NN/128, DD/64), 256>>>(gc, Wo, bo, out);
}

// round 3
// speedup vs baseline: 1.1639x; 1.1639x over previous
#include <cuda_runtime.h>
#include <cstdint>

#define BB  4
#define SS  2048
#define DD  1024
#define HH  16
#define DKK 64
#define NN  (BB*SS)
#define AST 68

// ---- warp-MMA GEMM tiling ----
#define BM   128
#define BN   128
#define BK   16
#define NIT  (DD/BK)            // 64
#define RS   20                 // smem row stride (floats), conflict-free
#define PLANE (BM*RS)           // 2560 floats per plane
#define STAGEF (4*PLANE)        // Ahi,Alo,Bhi,Blo
#define GEMM_SMEM (2*STAGEF*4)  // 81920 bytes

// scratch
__device__ float g_wt[DD*DD];   // transposed weights (K-major B)
__device__ float g_q[NN*DD];    // [B,S,H,DK] == [8192][1024]
__device__ float g_k[NN*DD];
__device__ float g_v[NN*DD];
__device__ float g_c[NN*DD];

__device__ __forceinline__ float tf32r(float x) {
    uint32_t u;
    asm("cvt.rna.tf32.f32 %0, %1;" : "=r"(u) : "f"(x));
    return __uint_as_float(u);
}
__device__ __forceinline__ void mma8(float* d, const float* a, const float* b) {
    asm volatile("mma.sync.aligned.m16n8k8.row.col.f32.tf32.tf32.f32 "
        "{%0,%1,%2,%3}, {%4,%5,%6,%7}, {%8,%9}, {%0,%1,%2,%3};"
        : "+f"(d[0]), "+f"(d[1]), "+f"(d[2]), "+f"(d[3])
        : "r"(__float_as_uint(a[0])), "r"(__float_as_uint(a[1])),
          "r"(__float_as_uint(a[2])), "r"(__float_as_uint(a[3])),
          "r"(__float_as_uint(b[0])), "r"(__float_as_uint(b[1])));
}

// ---------------------------------------------------------------------------
// Weight transpose: Wt[h*64+dk][d] = W[h][d][dk]
// ---------------------------------------------------------------------------
__global__ void transpose_w(const float* __restrict__ W, float* __restrict__ Wt) {
    __shared__ float t[32][33];
    const int h  = blockIdx.z;
    const int d0 = blockIdx.y << 5;
    const int k0 = blockIdx.x << 5;
    const int c  = threadIdx.x & 31;
    const int r4 = threadIdx.x >> 5;
    const float* Wh = W + ((size_t)h << 16);
    #pragma unroll
    for (int i = 0; i < 4; i++)
        t[r4 + 8*i][c] = Wh[(size_t)(d0 + r4 + 8*i) * DKK + k0 + c];
    __syncthreads();
    float* o = Wt + (size_t)(h * DKK + k0) * DD + d0;
    #pragma unroll
    for (int i = 0; i < 4; i++)
        o[(size_t)(r4 + 8*i) * DD + c] = t[c][r4 + 8*i];
}

// ---------------------------------------------------------------------------
// tf32x3 warp-MMA GEMM: C[m][n] = sum_k A[m][k]*B[n][k] (+bias[n])
// A:[8192x1024] B:[1024x1024] K-major, both fp32 split hi/lo on the fly.
// 256 threads, BM=128 BN=128 BK=16, warp tile 64x32, double-buffered smem.
// ---------------------------------------------------------------------------
__global__ __launch_bounds__(256, 1)
void gemm_tf32(const float* __restrict__ A, const float* __restrict__ B,
               const float* __restrict__ bias, float* __restrict__ C)
{
    extern __shared__ float sm[];
    const int tid  = threadIdx.x;
    const int m0   = blockIdx.y * BM;
    const int n0   = blockIdx.x * BN;
    const int w    = tid >> 5, lane = tid & 31;
    const int grp  = lane >> 2, tig = lane & 3;
    const int m_off = (w >> 2) * 64;      // warp m offset (0/64)
    const int n_off = (w & 3) * 32;       // warp n offset (0..96)

    // loader indices: 2 float4 per matrix per thread
    const int lrow0 = tid >> 2, lc4 = (tid & 3) * 4;
    const int lrow1 = lrow0 + 64;

    float acc[4][4][4];
    #pragma unroll
    for (int t = 0; t < 4; t++)
        #pragma unroll
        for (int u = 0; u < 4; u++)
            #pragma unroll
            for (int q = 0; q < 4; q++) acc[t][u][q] = 0.f;

    float4 ra0, ra1, rb0, rb1;
    // prologue load k0=0
    ra0 = *reinterpret_cast<const float4*>(A + (size_t)(m0 + lrow0) * DD + lc4);
    ra1 = *reinterpret_cast<const float4*>(A + (size_t)(m0 + lrow1) * DD + lc4);
    rb0 = *reinterpret_cast<const float4*>(B + (size_t)(n0 + lrow0) * DD + lc4);
    rb1 = *reinterpret_cast<const float4*>(B + (size_t)(n0 + lrow1) * DD + lc4);

    // split+store helper (macro to keep regs tight)
    #define SPLIT_STORE(stage)                                                    \
    {                                                                             \
        float* AHI = sm + (stage) * STAGEF;                                       \
        float* ALO = AHI + PLANE;                                                 \
        float* BHI = AHI + 2 * PLANE;                                             \
        float* BLO = AHI + 3 * PLANE;                                             \
        float4 h, l;                                                              \
        h.x=tf32r(ra0.x); l.x=tf32r(ra0.x-h.x); h.y=tf32r(ra0.y); l.y=tf32r(ra0.y-h.y); \
        h.z=tf32r(ra0.z); l.z=tf32r(ra0.z-h.z); h.w=tf32r(ra0.w); l.w=tf32r(ra0.w-h.w); \
        *reinterpret_cast<float4*>(AHI + lrow0*RS + lc4) = h;                     \
        *reinterpret_cast<float4*>(ALO + lrow0*RS + lc4) = l;                     \
        h.x=tf32r(ra1.x); l.x=tf32r(ra1.x-h.x); h.y=tf32r(ra1.y); l.y=tf32r(ra1.y-h.y); \
        h.z=tf32r(ra1.z); l.z=tf32r(ra1.z-h.z); h.w=tf32r(ra1.w); l.w=tf32r(ra1.w-h.w); \
        *reinterpret_cast<float4*>(AHI + lrow1*RS + lc4) = h;                     \
        *reinterpret_cast<float4*>(ALO + lrow1*RS + lc4) = l;                     \
        h.x=tf32r(rb0.x); l.x=tf32r(rb0.x-h.x); h.y=tf32r(rb0.y); l.y=tf32r(rb0.y-h.y); \
        h.z=tf32r(rb0.z); l.z=tf32r(rb0.z-h.z); h.w=tf32r(rb0.w); l.w=tf32r(rb0.w-h.w); \
        *reinterpret_cast<float4*>(BHI + lrow0*RS + lc4) = h;                     \
        *reinterpret_cast<float4*>(BLO + lrow0*RS + lc4) = l;                     \
        h.x=tf32r(rb1.x); l.x=tf32r(rb1.x-h.x); h.y=tf32r(rb1.y); l.y=tf32r(rb1.y-h.y); \
        h.z=tf32r(rb1.z); l.z=tf32r(rb1.z-h.z); h.w=tf32r(rb1.w); l.w=tf32r(rb1.w-h.w); \
        *reinterpret_cast<float4*>(BHI + lrow1*RS + lc4) = h;                     \
        *reinterpret_cast<float4*>(BLO + lrow1*RS + lc4) = l;                     \
    }

    SPLIT_STORE(0);
    __syncthreads();

    for (int c = 0; c < NIT; ++c) {
        if (c + 1 < NIT) {
            const int k0 = (c + 1) * BK;
            ra0 = *reinterpret_cast<const float4*>(A + (size_t)(m0 + lrow0) * DD + k0 + lc4);
            ra1 = *reinterpret_cast<const float4*>(A + (size_t)(m0 + lrow1) * DD + k0 + lc4);
            rb0 = *reinterpret_cast<const float4*>(B + (size_t)(n0 + lrow0) * DD + k0 + lc4);
            rb1 = *reinterpret_cast<const float4*>(B + (size_t)(n0 + lrow1) * DD + k0 + lc4);
        }

        const float* AHI = sm + (c & 1) * STAGEF;
        const float* ALO = AHI + PLANE;
        const float* BHI = AHI + 2 * PLANE;
        const float* BLO = AHI + 3 * PLANE;

        #pragma unroll
        for (int s = 0; s < 2; ++s) {
            const int kk = s * 8;
            float ah[4][4], al[4][4], bh[4][2], bl[4][2];
            #pragma unroll
            for (int t = 0; t < 4; t++) {
                const int r = m_off + t * 16 + grp;
                const int cidx = kk + tig;
                ah[t][0] = AHI[r*RS + cidx];       al[t][0] = ALO[r*RS + cidx];
                ah[t][1] = AHI[(r+8)*RS + cidx];   al[t][1] = ALO[(r+8)*RS + cidx];
                ah[t][2] = AHI[r*RS + cidx + 4];   al[t][2] = ALO[r*RS + cidx + 4];
                ah[t][3] = AHI[(r+8)*RS + cidx+4]; al[t][3] = ALO[(r+8)*RS + cidx+4];
            }
            #pragma unroll
            for (int u = 0; u < 4; u++) {
                const int n = n_off + u * 8 + grp;
                const int cidx = kk + tig;
                bh[u][0] = BHI[n*RS + cidx];     bl[u][0] = BLO[n*RS + cidx];
                bh[u][1] = BHI[n*RS + cidx + 4]; bl[u][1] = BLO[n*RS + cidx + 4];
            }
            #pragma unroll
            for (int t = 0; t < 4; t++)
                #pragma unroll
                for (int u = 0; u < 4; u++) {
                    mma8(acc[t][u], ah[t], bh[u]);
                    mma8(acc[t][u], ah[t], bl[u]);
                    mma8(acc[t][u], al[t], bh[u]);
                }
        }

        if (c + 1 < NIT) SPLIT_STORE((c + 1) & 1);
        __syncthreads();
    }

    // epilogue
    const bool hasb = (bias != nullptr);
    #pragma unroll
    for (int u = 0; u < 4; u++) {
        const int ncol = n0 + n_off + u * 8 + tig * 2;
        float2 bv = make_float2(0.f, 0.f);
        if (hasb) bv = *reinterpret_cast<const float2*>(bias + ncol);
        #pragma unroll
        for (int t = 0; t < 4; t++) {
            const int r = m0 + m_off + t * 16 + grp;
            *reinterpret_cast<float2*>(C + (size_t)r * DD + ncol) =
                make_float2(acc[t][u][0] + bv.x, acc[t][u][1] + bv.y);
            *reinterpret_cast<float2*>(C + (size_t)(r + 8) * DD + ncol) =
                make_float2(acc[t][u][2] + bv.x, acc[t][u][3] + bv.y);
        }
    }
    #undef SPLIT_STORE
}

// ---------------------------------------------------------------------------
// Causal flash attention, fp32 FFMA. q/k/v layout [B,S,H,DK] (row stride DD).
// ---------------------------------------------------------------------------
__global__ __launch_bounds__(256)
void attn_kernel(const float* __restrict__ gq, const float* __restrict__ gk,
                 const float* __restrict__ gv, float* __restrict__ gc)
{
    extern __shared__ float smf[];
    float* Qs = smf;
    float* Ks = smf + 64*AST;
    float* Vs = smf + 2*64*AST;
    float* Ps = smf + 3*64*AST;

    const int tid = threadIdx.x;
    const int ty  = tid >> 4, tx = tid & 15;
    const int h   = blockIdx.y, b = blockIdx.z;
    const int st  = gridDim.x - 1 - blockIdx.x;
    const int s0  = st * 64;
    const int r0  = ty * 4, c0 = tx * 4;

    const float* qb = gq + ((size_t)b * SS + s0) * DD + h * DKK;
    const float* kb = gk + (size_t)b * SS * DD + h * DKK;
    const float* vb = gv + (size_t)b * SS * DD + h * DKK;

    #pragma unroll
    for (int u = 0; u < 4; u++) {
        int f = tid + u * 256;
        int row = f >> 4, c4 = f & 15;
        *reinterpret_cast<float4*>(Qs + row*AST + c4*4) =
            *reinterpret_cast<const float4*>(qb + (size_t)row * DD + c4*4);
    }

    float m[4], l[4], o[4][4];
    #pragma unroll
    for (int i = 0; i < 4; i++) {
        m[i] = -1e30f; l[i] = 0.f;
        #pragma unroll
        for (int j = 0; j < 4; j++) o[i][j] = 0.f;
    }

    const int ntiles = st + 1;
    for (int tt = 0; tt < ntiles; ++tt) {
        const int t0 = tt * 64;
        __syncthreads();
        #pragma unroll
        for (int u = 0; u < 4; u++) {
            int f = tid + u * 256;
            int row = f >> 4, c4 = f & 15;
            float4 kv = *reinterpret_cast<const float4*>(kb + (size_t)(t0+row) * DD + c4*4);
            Ks[(c4*4+0)*AST + row] = kv.x;
            Ks[(c4*4+1)*AST + row] = kv.y;
            Ks[(c4*4+2)*AST + row] = kv.z;
            Ks[(c4*4+3)*AST + row] = kv.w;
            *reinterpret_cast<float4*>(Vs + row*AST + c4*4) =
                *reinterpret_cast<const float4*>(vb + (size_t)(t0+row) * DD + c4*4);
        }
        __syncthreads();

        float sv[4][4];
        #pragma unroll
        for (int i = 0; i < 4; i++)
            #pragma unroll
            for (int j = 0; j < 4; j++) sv[i][j] = 0.f;

        #pragma unroll 16
        for (int kk = 0; kk < 64; kk++) {
            float a[4];
            #pragma unroll
            for (int i = 0; i < 4; i++) a[i] = Qs[(r0+i)*AST + kk];
            float4 b4 = *reinterpret_cast<const float4*>(Ks + kk*AST + c0);
            float bv[4] = {b4.x, b4.y, b4.z, b4.w};
            #pragma unroll
            for (int i = 0; i < 4; i++)
                #pragma unroll
                for (int j = 0; j < 4; j++)
                    sv[i][j] = fmaf(a[i], bv[j], sv[i][j]);
        }

        #pragma unroll
        for (int i = 0; i < 4; i++)
            #pragma unroll
            for (int j = 0; j < 4; j++) sv[i][j] *= 8.0f;
        if (t0 == s0) {
            #pragma unroll
            for (int i = 0; i < 4; i++)
                #pragma unroll
                for (int j = 0; j < 4; j++)
                    if (c0 + j > r0 + i) sv[i][j] = -1e30f;
        }

        float mt[4];
        #pragma unroll
        for (int i = 0; i < 4; i++)
            mt[i] = fmaxf(fmaxf(sv[i][0], sv[i][1]), fmaxf(sv[i][2], sv[i][3]));
        #pragma unroll
        for (int off = 8; off; off >>= 1)
            #pragma unroll
            for (int i = 0; i < 4; i++)
                mt[i] = fmaxf(mt[i], __shfl_xor_sync(0xffffffffu, mt[i], off));

        float mn[4], alpha[4];
        #pragma unroll
        for (int i = 0; i < 4; i++) {
            mn[i] = fmaxf(m[i], mt[i]);
            alpha[i] = __expf(m[i] - mn[i]);
            m[i] = mn[i];
        }

        float p[4][4], ls[4];
        #pragma unroll
        for (int i = 0; i < 4; i++) {
            ls[i] = 0.f;
            #pragma unroll
            for (int j = 0; j < 4; j++) {
                p[i][j] = __expf(sv[i][j] - mn[i]);
                ls[i] += p[i][j];
            }
        }
        #pragma unroll
        for (int off = 8; off; off >>= 1)
            #pragma unroll
            for (int i = 0; i < 4; i++)
                ls[i] += __shfl_xor_sync(0xffffffffu, ls[i], off);

        #pragma unroll
        for (int i = 0; i < 4; i++) {
            l[i] = l[i] * alpha[i] + ls[i];
            #pragma unroll
            for (int j = 0; j < 4; j++) o[i][j] *= alpha[i];
        }

        #pragma unroll
        for (int i = 0; i < 4; i++)
            *reinterpret_cast<float4*>(Ps + (r0+i)*AST + c0) =
                make_float4(p[i][0], p[i][1], p[i][2], p[i][3]);
        __syncthreads();

        #pragma unroll 16
        for (int kk = 0; kk < 64; kk++) {
            float a[4];
            #pragma unroll
            for (int i = 0; i < 4; i++) a[i] = Ps[(r0+i)*AST + kk];
            float4 b4 = *reinterpret_cast<const float4*>(Vs + kk*AST + c0);
            float bv[4] = {b4.x, b4.y, b4.z, b4.w};
            #pragma unroll
            for (int i = 0; i < 4; i++)
                #pragma unroll
                for (int j = 0; j < 4; j++)
                    o[i][j] = fmaf(a[i], bv[j], o[i][j]);
        }
    }

    float* outp = gc + ((size_t)b * SS + s0) * DD + h * DKK;
    #pragma unroll
    for (int i = 0; i < 4; i++) {
        float inv = 1.0f / l[i];
        float4 ov = make_float4(o[i][0]*inv, o[i][1]*inv, o[i][2]*inv, o[i][3]*inv);
        *reinterpret_cast<float4*>(outp + (size_t)(r0+i) * DD + c0) = ov;
    }
}

// ---------------------------------------------------------------------------
extern "C" void kernel_launch(void* const* d_in, const int* in_sizes, int n_in,
                              void* d_out, int out_size)
{
    const float* Q  = (const float*)d_in[0];
    const float* K  = (const float*)d_in[1];
    const float* V  = (const float*)d_in[2];
    // d_in[3] = causal mask (unused)
    const float* Wq = (const float*)d_in[4];
    const float* Wk = (const float*)d_in[5];
    const float* Wv = (const float*)d_in[6];
    const float* Wo = (const float*)d_in[7];
    const float* bo = (const float*)d_in[8];
    float* out = (float*)d_out;

    float *gwt, *gq, *gk, *gv, *gc;
    cudaGetSymbolAddress((void**)&gwt, g_wt);
    cudaGetSymbolAddress((void**)&gq,  g_q);
    cudaGetSymbolAddress((void**)&gk,  g_k);
    cudaGetSymbolAddress((void**)&gv,  g_v);
    cudaGetSymbolAddress((void**)&gc,  g_c);

    cudaFuncSetAttribute(gemm_tf32, cudaFuncAttributeMaxDynamicSharedMemorySize, GEMM_SMEM);
    int asmem = 4 * 64 * AST * (int)sizeof(float);
    cudaFuncSetAttribute(attn_kernel, cudaFuncAttributeMaxDynamicSharedMemorySize, asmem);

    const dim3 tg(DKK / 32, DD / 32, HH);     // (2, 32, 16)
    const dim3 gg(DD / BN, NN / BM);          // (8, 64)

    transpose_w<<<tg, 256>>>(Wq, gwt);
    gemm_tf32<<<gg, 256, GEMM_SMEM>>>(Q, gwt, nullptr, gq);
    transpose_w<<<tg, 256>>>(Wk, gwt);
    gemm_tf32<<<gg, 256, GEMM_SMEM>>>(K, gwt, nullptr, gk);
    transpose_w<<<tg, 256>>>(Wv, gwt);
    gemm_tf32<<<gg, 256, GEMM_SMEM>>>(V, gwt, nullptr, gv);

    attn_kernel<<<dim3(SS/64, HH, BB), 256, asmem>>>(gq, gk, gv, gc);

    gemm_tf32<<<gg, 256, GEMM_SMEM>>>(gc, Wo, bo, out);
}